// round 11
// baseline (speedup 1.0000x reference)
#include <cuda_runtime.h>
#include <cstdint>

// SM-2 scan: R5 geometry (proven optimum: 128 thr / 4 warps / 2 rows/thread,
// CHUNK=16, stride-20, 2-stage cp.async double buffer, 5 blocks/SM) with the
// carried-predicate step (R==1 test replaced by previous step's correct-flag,
// exact equivalence). Plain cp.async.cg — the L2::256B hint measured as a
// +30MB DRAM-traffic regression in R10 and is removed.

static constexpr int STEPS          = 400;
static constexpr int RPW            = 64;
static constexpr int WARPS          = 4;
static constexpr int THREADS        = 32 * WARPS;          // 128
static constexpr int ROWS_PER_BLOCK = RPW * WARPS;         // 256
static constexpr int CHUNK          = 16;
static constexpr int NCHUNK         = STEPS / CHUNK;       // 25 exact
static constexpr int STRIDE         = CHUNK + 4;           // 20: conflict-free LDS.128
static constexpr int WBUF           = RPW * STRIDE;        // 1280 floats
static constexpr int SMEM_BYTES     = WARPS * 2 * WBUF * (int)sizeof(float); // 40960

__device__ __forceinline__ uint32_t smem_u32(const void* p) {
    return (uint32_t)__cvta_generic_to_shared(p);
}
__device__ __forceinline__ void cp_async16(uint32_t saddr, const void* gptr) {
    asm volatile("cp.async.cg.shared.global [%0], [%1], 16;\n" :: "r"(saddr), "l"(gptr));
}
__device__ __forceinline__ void cp_commit() {
    asm volatile("cp.async.commit_group;\n" ::: "memory");
}
template <int N>
__device__ __forceinline__ void cp_wait() {
    asm volatile("cp.async.wait_group %0;\n" :: "n"(N) : "memory");
}

// Packed f32x2 helpers (sm_103a FFMA2/FMUL2/FADD2 via PTX).
union F2 { float f[2]; unsigned long long u; };
__device__ __forceinline__ F2 mk2(float a, float b) { F2 r; r.f[0] = a; r.f[1] = b; return r; }
__device__ __forceinline__ F2 mul2(F2 a, F2 b) {
    F2 d; asm("mul.rn.f32x2 %0, %1, %2;" : "=l"(d.u) : "l"(a.u), "l"(b.u)); return d;
}
__device__ __forceinline__ F2 add2(F2 a, F2 b) {
    F2 d; asm("add.rn.f32x2 %0, %1, %2;" : "=l"(d.u) : "l"(a.u), "l"(b.u)); return d;
}
__device__ __forceinline__ F2 fma2(F2 a, F2 b, F2 c) {
    F2 d; asm("fma.rn.f32x2 %0, %1, %2, %3;" : "=l"(d.u) : "l"(a.u), "l"(b.u), "l"(c.u)); return d;
}

// Step for two rows; qa/qb carry the previous step's correct-flag.
// R = interval a correct answer yields next step; R==1 <=> prev incorrect,
// replaced by qa/qb (exact: any product path >= 6 on a surviving run).
// Upper clamp deferred to output (EF >= 1.3 keeps the product monotone).
__device__ __forceinline__ void sm2_step2(float pa, float pb,
                                          F2& I, F2& EF, F2& R, bool& qa, bool& qb) {
    const bool ca = pa >= 0.6f;          // == (p*5 >= 3) in RN
    const bool cb = pb >= 0.6f;

    float Ia = ca ? R.f[0] : 1.0f;
    float Ib = cb ? R.f[1] : 1.0f;

    F2 p = mk2(pa, pb);
    F2 w = fma2(p, mk2(-0.5f, -0.5f), mk2(1.4f, 1.4f));
    F2 u = fma2(p, w, mk2(-0.8f, -0.8f));   // 0.1-(5-q)(0.08+(5-q)*0.02), q=5p
    F2 EFn = add2(EF, u);
    EFn.f[0] = fmaxf(EFn.f[0], 1.3f);
    EFn.f[1] = fmaxf(EFn.f[1], 1.3f);
    EF.f[0] = ca ? EFn.f[0] : EF.f[0];
    EF.f[1] = cb ? EFn.f[1] : EF.f[1];

    I = mk2(Ia, Ib);
    F2 t = mul2(I, EF);                  // I*EF with next step's entry values
    R.f[0] = ca ? (qa ? t.f[0] : 6.0f) : 1.0f;
    R.f[1] = cb ? (qb ? t.f[1] : 6.0f) : 1.0f;

    qa = ca; qb = cb;
}

extern __shared__ float sbuf[];

__global__ void __launch_bounds__(THREADS, 5)
sm2_scan_kernel(const float* __restrict__ hist, float* __restrict__ out, int B) {
    const int lane  = threadIdx.x & 31;
    const int warp  = threadIdx.x >> 5;
    const int wrow0 = blockIdx.x * ROWS_PER_BLOCK + warp * RPW;

    float* buf0 = sbuf + warp * (2 * WBUF);
    float* buf1 = buf0 + WBUF;

    const float* g = hist + (size_t)wrow0 * STEPS;
    const bool full = (wrow0 + RPW <= B);

    auto load_chunk = [&](float* buf, int c0) {
        #pragma unroll
        for (int s = 0; s < 8; s++) {
            int f = s * 32 + lane;
            int r = f >> 2, k = f & 3;
            if (full || wrow0 + r < B)
                cp_async16(smem_u32(buf + r * STRIDE + k * 4),
                           g + (size_t)r * STEPS + c0 + k * 4);
        }
    };

    F2 I  = mk2(1.0f, 1.0f);
    F2 EF = mk2(2.5f, 2.5f);
    F2 R  = mk2(1.0f, 1.0f);
    bool qa = false, qb = false;         // start: "prev incorrect" (R==1)

    load_chunk(buf0, 0);
    cp_commit();

    const int ra = lane, rb = lane + 32;

    #pragma unroll 1
    for (int c = 0; c < NCHUNK; c++) {
        float* cur = (c & 1) ? buf1 : buf0;
        float* nxt = (c & 1) ? buf0 : buf1;
        if (c + 1 < NCHUNK) {
            load_chunk(nxt, (c + 1) * CHUNK);
            cp_commit();
            cp_wait<1>();
        } else {
            cp_wait<0>();
        }
        __syncwarp();

        const float* ma = cur + ra * STRIDE;
        const float* mb = cur + rb * STRIDE;
        #pragma unroll
        for (int j = 0; j < CHUNK / 4; j++) {
            float4 va = *reinterpret_cast<const float4*>(ma + 4 * j);
            float4 vb = *reinterpret_cast<const float4*>(mb + 4 * j);
            sm2_step2(va.x, vb.x, I, EF, R, qa, qb);
            sm2_step2(va.y, vb.y, I, EF, R, qa, qb);
            sm2_step2(va.z, vb.z, I, EF, R, qa, qb);
            sm2_step2(va.w, vb.w, I, EF, R, qa, qb);
        }
        __syncwarp();          // protect cur before next iteration overwrites it
    }

    if (wrow0 + ra < B) out[wrow0 + ra] = fminf(I.f[0], 274.0f);  // h_t = I
    if (wrow0 + rb < B) out[wrow0 + rb] = fminf(I.f[1], 274.0f);
}

extern "C" void kernel_launch(void* const* d_in, const int* in_sizes, int n_in,
                              void* d_out, int out_size) {
    const float* hist = (const float*)d_in[0];
    float* out = (float*)d_out;
    int B = out_size;

    cudaFuncSetAttribute(sm2_scan_kernel,
                         cudaFuncAttributeMaxDynamicSharedMemorySize, SMEM_BYTES);

    int blocks = (B + ROWS_PER_BLOCK - 1) / ROWS_PER_BLOCK;
    sm2_scan_kernel<<<blocks, THREADS, SMEM_BYTES>>>(hist, out, B);
}